// round 4
// baseline (speedup 1.0000x reference)
#include <cuda_runtime.h>
#include <math.h>
#include <stdint.h>

#define BB 8
#define CC 96
#define NN 3136
#define KK 9

// ---------------- scratch (device globals: no allocations allowed) ----------
__device__ float g_y1[BB*CC*NN];
__device__ float g_y1t[BB*NN*CC];
__device__ float g_xnt[BB*NN*CC];
__device__ int   g_idx[BB*NN*KK];
__device__ float g_cat[BB*2*CC*NN];
__device__ float g_y2[BB*2*CC*NN];
__device__ float g_t [BB*4*CC*NN];
__device__ float g_s1[BB*CC*NN];
__device__ float g_s2[BB*CC*NN];

// ---------------- generic 1x1-conv GEMM: out[b,o,n] = sum_c W[o,c] in[b,c,n] + bias[o]
#define TN 128
#define TO 32
#define TKC 32
__global__ void gemm_bias_kernel(const float* __restrict__ in, const float* __restrict__ W,
                                 const float* __restrict__ bias, float* __restrict__ out,
                                 int Cin, int Cout)
{
    int b  = blockIdx.z;
    int o0 = blockIdx.y * TO;
    int n0 = blockIdx.x * TN;
    const float* inb = in + (size_t)b * Cin * NN;
    float* outb      = out + (size_t)b * Cout * NN;

    __shared__ float Ws[TKC][TO + 1];
    __shared__ float Is[TKC][TN];

    int tid = threadIdx.x;
    int tx = tid & 31;
    int ty = tid >> 5;

    float acc[4][4];
    #pragma unroll
    for (int i = 0; i < 4; i++)
        #pragma unroll
        for (int j = 0; j < 4; j++) acc[i][j] = 0.f;

    for (int k0 = 0; k0 < Cin; k0 += TKC) {
        for (int i = tid; i < TO * TKC; i += 256) {
            int o = i >> 5, k = i & 31;
            Ws[k][o] = W[(size_t)(o0 + o) * Cin + k0 + k];
        }
        for (int i = tid; i < TKC * TN; i += 256) {
            int k = i >> 7, n = i & 127;
            int gn = n0 + n;
            Is[k][n] = (gn < NN) ? inb[(size_t)(k0 + k) * NN + gn] : 0.f;
        }
        __syncthreads();
        #pragma unroll 8
        for (int k = 0; k < TKC; k++) {
            float a0 = Ws[k][ty*4+0], a1 = Ws[k][ty*4+1];
            float a2 = Ws[k][ty*4+2], a3 = Ws[k][ty*4+3];
            float4 bv = *(const float4*)&Is[k][tx*4];
            acc[0][0] += a0*bv.x; acc[0][1] += a0*bv.y; acc[0][2] += a0*bv.z; acc[0][3] += a0*bv.w;
            acc[1][0] += a1*bv.x; acc[1][1] += a1*bv.y; acc[1][2] += a1*bv.z; acc[1][3] += a1*bv.w;
            acc[2][0] += a2*bv.x; acc[2][1] += a2*bv.y; acc[2][2] += a2*bv.z; acc[2][3] += a2*bv.w;
            acc[3][0] += a3*bv.x; acc[3][1] += a3*bv.y; acc[3][2] += a3*bv.z; acc[3][3] += a3*bv.w;
        }
        __syncthreads();
    }
    #pragma unroll
    for (int i = 0; i < 4; i++) {
        int o = o0 + ty*4 + i;
        float bb = bias[o];
        #pragma unroll
        for (int j = 0; j < 4; j++) {
            int n = n0 + tx*4 + j;
            if (n < NN) outb[(size_t)o * NN + n] = acc[i][j] + bb;
        }
    }
}

// ---------------- instance norm over N per (b,c) row, with fused epilogues
// EPI: 0=none, 1=gelu(exact), 2=relu, 3=add residual
#define NN4 (NN/4)
template<int EPI>
__global__ void inorm_kernel(const float* __restrict__ in, float* __restrict__ out,
                             const float* __restrict__ res)
{
    int row = blockIdx.x;
    const float4* x4 = (const float4*)(in + (size_t)row * NN);
    float4* y4       = (float4*)(out + (size_t)row * NN);
    const float4* r4 = res ? (const float4*)(res + (size_t)row * NN) : nullptr;

    float s = 0.f, ss = 0.f;
    for (int i = threadIdx.x; i < NN4; i += blockDim.x) {
        float4 v = x4[i];
        s  += v.x + v.y + v.z + v.w;
        ss += v.x*v.x + v.y*v.y + v.z*v.z + v.w*v.w;
    }
    __shared__ float red[2][32];
    #pragma unroll
    for (int o = 16; o; o >>= 1) {
        s  += __shfl_down_sync(0xffffffffu, s,  o);
        ss += __shfl_down_sync(0xffffffffu, ss, o);
    }
    int wid = threadIdx.x >> 5, lid = threadIdx.x & 31;
    if (!lid) { red[0][wid] = s; red[1][wid] = ss; }
    __syncthreads();
    if (wid == 0) {
        s  = (lid < (int)(blockDim.x >> 5)) ? red[0][lid] : 0.f;
        ss = (lid < (int)(blockDim.x >> 5)) ? red[1][lid] : 0.f;
        #pragma unroll
        for (int o = 16; o; o >>= 1) {
            s  += __shfl_down_sync(0xffffffffu, s,  o);
            ss += __shfl_down_sync(0xffffffffu, ss, o);
        }
        if (!lid) { red[0][0] = s; red[1][0] = ss; }
    }
    __syncthreads();
    float mean = red[0][0] * (1.f / NN);
    float var  = red[1][0] * (1.f / NN) - mean * mean;
    float rstd = rsqrtf(var + 1e-5f);
    for (int i = threadIdx.x; i < NN4; i += blockDim.x) {
        float4 v = x4[i];
        float o0 = (v.x - mean) * rstd, o1 = (v.y - mean) * rstd;
        float o2 = (v.z - mean) * rstd, o3 = (v.w - mean) * rstd;
        if (EPI == 1) {
            o0 = 0.5f*o0*(1.f + erff(o0*0.70710678118654752f));
            o1 = 0.5f*o1*(1.f + erff(o1*0.70710678118654752f));
            o2 = 0.5f*o2*(1.f + erff(o2*0.70710678118654752f));
            o3 = 0.5f*o3*(1.f + erff(o3*0.70710678118654752f));
        } else if (EPI == 2) {
            o0 = fmaxf(o0, 0.f); o1 = fmaxf(o1, 0.f);
            o2 = fmaxf(o2, 0.f); o3 = fmaxf(o3, 0.f);
        } else if (EPI == 3) {
            float4 r = r4[i];
            o0 += r.x; o1 += r.y; o2 += r.z; o3 += r.w;
        }
        y4[i] = make_float4(o0, o1, o2, o3);
    }
}

// ---------------- per-pixel L2 normalization -> TRANSPOSED output [b][n][c]
__global__ void colnorm_t_kernel(const float* __restrict__ y1, float* __restrict__ xnt)
{
    int b = blockIdx.y;
    int n = blockIdx.x * blockDim.x + threadIdx.x;
    if (n >= NN) return;
    const float* p = y1 + (size_t)b * CC * NN + n;
    float v[CC];
    float s = 0.f;
    #pragma unroll
    for (int c = 0; c < CC; c++) { v[c] = p[(size_t)c * NN]; s += v[c] * v[c]; }
    float rn = 1.f / fmaxf(sqrtf(s), 1e-12f);
    float4* q = (float4*)(xnt + ((size_t)b * NN + n) * CC);
    #pragma unroll
    for (int cq = 0; cq < CC/4; cq++)
        q[cq] = make_float4(v[4*cq]*rn, v[4*cq+1]*rn, v[4*cq+2]*rn, v[4*cq+3]*rn);
}

// ---------------- tiled transpose: [b][C][N] -> [b][N][C]
__global__ void transpose_kernel(const float* __restrict__ in, float* __restrict__ out)
{
    __shared__ float tile[32][33];
    int b  = blockIdx.z;
    int n0 = blockIdx.x * 32;
    int c0 = blockIdx.y * 32;
    int x = threadIdx.x, y = threadIdx.y;   // 32 x 8
    #pragma unroll
    for (int i = 0; i < 32; i += 8) {
        int c = c0 + y + i, n = n0 + x;
        tile[y + i][x] = (c < CC && n < NN) ? in[(size_t)b*CC*NN + (size_t)c*NN + n] : 0.f;
    }
    __syncthreads();
    #pragma unroll
    for (int i = 0; i < 32; i += 8) {
        int n = n0 + y + i, c = c0 + x;
        if (n < NN && c < CC)
            out[(size_t)b*NN*CC + (size_t)n*CC + c] = tile[x][y + i];
    }
}

// ---------------- 3xTF32 MMA kNN: fused distance GEMM + top-9 from fragments --
// score(n,m) = rp[n,m] - 2*dot(xn_n, xn_m)
// x = xh + xl (tf32 split); dot = xh*yh + xh*yl + xl*yh  (error ~2^-22)
#define KTR 128
#define KTC 128
#define AST 104                               // smem row stride (floats), conflict-free LDS.64
#define PL  (KTR*AST)                         // plane size
#define SMEM_KNN (4 * PL * 4)                 // Ah, Al, Bh, Bl planes

__device__ __forceinline__ unsigned f2tf(float v) {
    unsigned r;
    asm("cvt.rna.tf32.f32 %0, %1;" : "=r"(r) : "f"(v));
    return r;
}

__device__ __forceinline__ void mma_tf32(float c[4],
    unsigned a0, unsigned a1, unsigned a2, unsigned a3, unsigned b0, unsigned b1)
{
    asm volatile(
        "mma.sync.aligned.m16n8k8.row.col.f32.tf32.tf32.f32 "
        "{%0,%1,%2,%3},{%4,%5,%6,%7},{%8,%9},{%0,%1,%2,%3};"
        : "+f"(c[0]), "+f"(c[1]), "+f"(c[2]), "+f"(c[3])
        : "r"(a0), "r"(a1), "r"(a2), "r"(a3), "r"(b0), "r"(b1));
}

__device__ __forceinline__ void ins9(float (&bv)[KK], int (&bi)[KK], float s, int c)
{
    if (s < bv[KK-1]) {
        bv[KK-1] = s; bi[KK-1] = c;
        #pragma unroll
        for (int k = KK-1; k > 0; k--) {
            if (bv[k] < bv[k-1]) {
                float tv = bv[k]; bv[k] = bv[k-1]; bv[k-1] = tv;
                int   ti = bi[k]; bi[k] = bi[k-1]; bi[k-1] = ti;
            }
        }
    }
}

// stage one row-quad of 4 values into hi/lo planes with k-pair permutation:
// element k -> pos 2*(k&3) + ((k>>2)&1) within its 8-group
__device__ __forceinline__ void stage4(unsigned* Ph, unsigned* Pl, int base, float4 v)
{
    unsigned hx = f2tf(v.x), hy = f2tf(v.y), hz = f2tf(v.z), hw = f2tf(v.w);
    Ph[base + 0] = hx; Ph[base + 2] = hy; Ph[base + 4] = hz; Ph[base + 6] = hw;
    Pl[base + 0] = f2tf(v.x - __uint_as_float(hx));
    Pl[base + 2] = f2tf(v.y - __uint_as_float(hy));
    Pl[base + 4] = f2tf(v.z - __uint_as_float(hz));
    Pl[base + 6] = f2tf(v.w - __uint_as_float(hw));
}

__global__ void __launch_bounds__(512, 1)
knn_mma_kernel(const float* __restrict__ xnt, const float* __restrict__ rp,
               int* __restrict__ idx)
{
    extern __shared__ unsigned smu[];
    unsigned* Ah = smu;
    unsigned* Al = smu + PL;
    unsigned* Bh = smu + 2 * PL;
    unsigned* Bl = smu + 3 * PL;

    int b  = blockIdx.y;
    int r0 = blockIdx.x * KTR;
    const float* xb = xnt + (size_t)b * NN * CC;
    int tid  = threadIdx.x;
    int warp = tid >> 5, lane = tid & 31;
    int g = lane >> 2, th = lane & 3;
    int wrow = (warp >> 1) * 16;
    int cw   = warp & 1;

    // ---- stage A tile (rows r0..r0+127)
    for (int i4 = tid; i4 < KTR * (CC/4); i4 += 512) {
        int r = i4 / (CC/4), cq = i4 % (CC/4);
        int c0 = cq * 4;
        int base = r * AST + (c0 & ~7) + ((c0 >> 2) & 1);
        float4 v = make_float4(0.f, 0.f, 0.f, 0.f);
        if (r0 + r < NN) v = *(const float4*)&xb[(size_t)(r0 + r) * CC + c0];
        stage4(Ah, Al, base, v);
    }

    float best0[KK], best1[KK]; int bidx0[KK], bidx1[KK];
    #pragma unroll
    for (int k = 0; k < KK; k++) {
        best0[k] = 3.4e38f; bidx0[k] = 0;
        best1[k] = 3.4e38f; bidx1[k] = 0;
    }

    int r1 = r0 + wrow + g, r2 = r1 + 8;
    int rc1 = (r1 < NN) ? r1 : (NN - 1);
    int rc2 = (r2 < NN) ? r2 : (NN - 1);

    for (int m0 = 0; m0 < NN; m0 += KTC) {
        // ---- stage B tile (cols m0..m0+127)
        for (int i4 = tid; i4 < KTC * (CC/4); i4 += 512) {
            int r = i4 / (CC/4), cq = i4 % (CC/4);
            int c0 = cq * 4;
            int base = r * AST + (c0 & ~7) + ((c0 >> 2) & 1);
            float4 v = make_float4(0.f, 0.f, 0.f, 0.f);
            if (m0 + r < NN) v = *(const float4*)&xb[(size_t)(m0 + r) * CC + c0];
            stage4(Bh, Bl, base, v);
        }
        __syncthreads();

        float C[8][4];
        #pragma unroll
        for (int f = 0; f < 8; f++)
            #pragma unroll
            for (int j = 0; j < 4; j++) C[f][j] = 0.f;

        for (int ks = 0; ks < 12; ks++) {
            int k0 = ks * 8;
            int offA = (wrow + g) * AST + k0 + 2*th;
            uint2 a01h = *(const uint2*)&Ah[offA];
            uint2 a23h = *(const uint2*)&Ah[offA + 8*AST];
            uint2 a01l = *(const uint2*)&Al[offA];
            uint2 a23l = *(const uint2*)&Al[offA + 8*AST];
            #pragma unroll
            for (int f = 0; f < 8; f++) {
                int offB = (cw*64 + f*8 + g) * AST + k0 + 2*th;
                uint2 bh = *(const uint2*)&Bh[offB];
                uint2 bl = *(const uint2*)&Bl[offB];
                mma_tf32(C[f], a01h.x, a23h.x, a01h.y, a23h.y, bh.x, bh.y);
                mma_tf32(C[f], a01h.x, a23h.x, a01h.y, a23h.y, bl.x, bl.y);
                mma_tf32(C[f], a01l.x, a23l.x, a01l.y, a23l.y, bh.x, bh.y);
            }
        }

        // ---- selection straight from fragments
        #pragma unroll
        for (int f = 0; f < 8; f++) {
            int nb = cw * 64 + f * 8;
            if (m0 + nb < NN) {
                int gm = m0 + nb + 2 * th;
                float2 p1 = *(const float2*)&rp[(size_t)rc1 * NN + gm];
                float2 p2 = *(const float2*)&rp[(size_t)rc2 * NN + gm];
                ins9(best0, bidx0, p1.x - 2.f * C[f][0], gm);
                ins9(best0, bidx0, p1.y - 2.f * C[f][1], gm + 1);
                ins9(best1, bidx1, p2.x - 2.f * C[f][2], gm);
                ins9(best1, bidx1, p2.y - 2.f * C[f][3], gm + 1);
            }
        }
        __syncthreads();   // B planes free for next stage
    }

    // ---- merge 8 partial lists per row through smem (reuse tile memory)
    float* mv = (float*)smu;                       // [KTR][8][9]
    int*   mi = (int*)(smu + KTR * 8 * KK);        // [KTR][8][9]
    int list = cw * 4 + th;
    #pragma unroll
    for (int k = 0; k < KK; k++) {
        mv[((wrow + g)     * 8 + list) * KK + k] = best0[k];
        mi[((wrow + g)     * 8 + list) * KK + k] = bidx0[k];
        mv[((wrow + g + 8) * 8 + list) * KK + k] = best1[k];
        mi[((wrow + g + 8) * 8 + list) * KK + k] = bidx1[k];
    }
    __syncthreads();

    if (tid < KTR && r0 + tid < NN) {
        int ptr[8] = {0,0,0,0,0,0,0,0};
        int* op = idx + ((size_t)b * NN + r0 + tid) * KK;
        #pragma unroll
        for (int k = 0; k < KK; k++) {
            float bv = 3.5e38f; int bi = 0x7fffffff; int bq = 0;
            #pragma unroll
            for (int q = 0; q < 8; q++) {
                if (ptr[q] < KK) {
                    float v = mv[(tid * 8 + q) * KK + ptr[q]];
                    int   i = mi[(tid * 8 + q) * KK + ptr[q]];
                    if (v < bv || (v == bv && i < bi)) { bv = v; bi = i; bq = q; }
                }
            }
            op[k] = bi;
            ptr[bq]++;
        }
    }
}

// ---------------- max-relative gather (from transposed features) + interleaved concat
__global__ void gather2_kernel(const float* __restrict__ y1t, const int* __restrict__ idx,
                               float* __restrict__ cat)
{
    int b = blockIdx.y;
    int n = blockIdx.x * blockDim.x + threadIdx.x;
    if (n >= NN) return;
    const int* ib = idx + ((size_t)b * NN + n) * KK;
    int j[KK];
    #pragma unroll
    for (int k = 0; k < KK; k++) j[k] = ib[k];

    const float4* base = (const float4*)(y1t + (size_t)b * NN * CC);
    const float4* own  = base + (size_t)n * (CC/4);
    float* cb = cat + (size_t)b * 2 * CC * NN + n;

    #pragma unroll 2
    for (int cc = 0; cc < CC/4; cc++) {
        float4 o = own[cc];
        float4 m = base[(size_t)j[0] * (CC/4) + cc];
        #pragma unroll
        for (int k = 1; k < KK; k++) {
            float4 v = base[(size_t)j[k] * (CC/4) + cc];
            m.x = fmaxf(m.x, v.x); m.y = fmaxf(m.y, v.y);
            m.z = fmaxf(m.z, v.z); m.w = fmaxf(m.w, v.w);
        }
        cb[(size_t)(8*cc + 0) * NN] = o.x;
        cb[(size_t)(8*cc + 1) * NN] = m.x - o.x;
        cb[(size_t)(8*cc + 2) * NN] = o.y;
        cb[(size_t)(8*cc + 3) * NN] = m.y - o.y;
        cb[(size_t)(8*cc + 4) * NN] = o.z;
        cb[(size_t)(8*cc + 5) * NN] = m.z - o.z;
        cb[(size_t)(8*cc + 6) * NN] = o.w;
        cb[(size_t)(8*cc + 7) * NN] = m.w - o.w;
    }
}

// ---------------- host orchestration -----------------------------------------
static void run_grapher(const float* X, const float* rp,
                        const float* fc1w, const float* fc1b,
                        const float* mrw,  const float* mrb,
                        const float* fc2w, const float* fc2b,
                        float* out,
                        float* y1, float* y1t, float* xnt, int* idx,
                        float* cat, float* y2, float* t)
{
    dim3 gA((NN + TN - 1) / TN, CC / TO, BB);
    gemm_bias_kernel<<<gA, 256>>>(X, fc1w, fc1b, y1, CC, CC);
    inorm_kernel<0><<<BB * CC, 256>>>(y1, y1, nullptr);
    colnorm_t_kernel<<<dim3((NN + 255) / 256, BB), 256>>>(y1, xnt);
    transpose_kernel<<<dim3((NN + 31) / 32, (CC + 31) / 32, BB), dim3(32, 8)>>>(y1, y1t);
    knn_mma_kernel<<<dim3((NN + KTR - 1) / KTR, BB), 512, SMEM_KNN>>>(xnt, rp, idx);
    gather2_kernel<<<dim3((NN + 255) / 256, BB), 256>>>(y1t, idx, cat);
    dim3 gB((NN + TN - 1) / TN, 2 * CC / TO, BB);
    gemm_bias_kernel<<<gB, 256>>>(cat, mrw, mrb, y2, 2 * CC, 2 * CC);
    inorm_kernel<1><<<BB * 2 * CC, 256>>>(y2, y2, nullptr);
    dim3 gC((NN + TN - 1) / TN, CC / TO, BB);
    gemm_bias_kernel<<<gC, 256>>>(y2, fc2w, fc2b, t, 2 * CC, CC);
    inorm_kernel<3><<<BB * CC, 256>>>(t, out, X);
}

static void run_ffn(const float* X,
                    const float* w1, const float* b1,
                    const float* w2, const float* b2,
                    float* out, float* t, float* y1)
{
    dim3 gA((NN + TN - 1) / TN, 4 * CC / TO, BB);
    gemm_bias_kernel<<<gA, 256>>>(X, w1, b1, t, CC, 4 * CC);
    inorm_kernel<1><<<BB * 4 * CC, 256>>>(t, t, nullptr);
    dim3 gB((NN + TN - 1) / TN, CC / TO, BB);
    gemm_bias_kernel<<<gB, 256>>>(t, w2, b2, y1, 4 * CC, CC);
    inorm_kernel<3><<<BB * CC, 256>>>(y1, out, X);
}

extern "C" void kernel_launch(void* const* d_in, const int* in_sizes, int n_in,
                              void* d_out, int out_size)
{
    const float* X0 = (const float*)d_in[0];
    const float* rp = (const float*)d_in[1];

    float *y1, *y1t, *xnt, *cat, *y2, *t, *s1, *s2; int* idx;
    cudaGetSymbolAddress((void**)&y1,  g_y1);
    cudaGetSymbolAddress((void**)&y1t, g_y1t);
    cudaGetSymbolAddress((void**)&xnt, g_xnt);
    cudaGetSymbolAddress((void**)&idx, g_idx);
    cudaGetSymbolAddress((void**)&cat, g_cat);
    cudaGetSymbolAddress((void**)&y2,  g_y2);
    cudaGetSymbolAddress((void**)&t,   g_t);
    cudaGetSymbolAddress((void**)&s1,  g_s1);
    cudaGetSymbolAddress((void**)&s2,  g_s2);

    cudaFuncSetAttribute(knn_mma_kernel, cudaFuncAttributeMaxDynamicSharedMemorySize, SMEM_KNN);

    // grapher 1: X0 -> s1
    run_grapher(X0, rp,
                (const float*)d_in[2], (const float*)d_in[3],
                (const float*)d_in[4], (const float*)d_in[5],
                (const float*)d_in[6], (const float*)d_in[7],
                s1, y1, y1t, xnt, idx, cat, y2, t);
    // ffn 1: s1 -> s2
    run_ffn(s1,
            (const float*)d_in[14], (const float*)d_in[15],
            (const float*)d_in[16], (const float*)d_in[17],
            s2, t, y1);
    // mid: relu(inorm(s2)) -> s1
    inorm_kernel<2><<<BB * CC, 256>>>(s2, s1, nullptr);
    // grapher 2: s1 -> s2
    run_grapher(s1, rp,
                (const float*)d_in[8],  (const float*)d_in[9],
                (const float*)d_in[10], (const float*)d_in[11],
                (const float*)d_in[12], (const float*)d_in[13],
                s2, y1, y1t, xnt, idx, cat, y2, t);
    // ffn 2: s2 -> s1
    run_ffn(s2,
            (const float*)d_in[18], (const float*)d_in[19],
            (const float*)d_in[20], (const float*)d_in[21],
            s1, t, y1);
    // final: out = X0 + inorm(s1)
    inorm_kernel<3><<<BB * CC, 256>>>(s1, (float*)d_out, X0);
}